// round 1
// baseline (speedup 1.0000x reference)
#include <cuda_runtime.h>

#define NVERT 6890
#define NJ 24
#define NB 10
#define NP 207
#define MAXB 1024
#define TB 16

__constant__ int c_par[NJ] = {-1, 0, 0, 0, 1, 2, 3, 4, 5, 6, 7, 8, 9, 9, 9,
                              12, 13, 14, 16, 17, 18, 19, 20, 21};

// Scratch (no allocations allowed)
__device__ float g_JrT[NJ * 3];           // J_regressor @ v_template
__device__ float g_JrS[NJ * 3 * NB];      // J_regressor @ shapedirs  [j][c][s]
__device__ float g_G[MAXB * NJ * 12];     // skinning transforms (3x4 row-major, cols 0..3)
__device__ float g_lrot[MAXB * NP];       // pose blend coefficients

// ---------------------------------------------------------------------------
// Kernel A: fold J_regressor into v_template and shapedirs.
// grid = NJ blocks, 256 threads. Each block j reduces over all vertices.
// ---------------------------------------------------------------------------
__global__ __launch_bounds__(256) void kA(const float* __restrict__ Jr,
                                          const float* __restrict__ vt,
                                          const float* __restrict__ sd) {
    int j = blockIdx.x;
    float acc[33];
#pragma unroll
    for (int k = 0; k < 33; ++k) acc[k] = 0.f;

    for (int v = threadIdx.x; v < NVERT; v += blockDim.x) {
        float w = Jr[j * NVERT + v];
        const float* vtp = vt + v * 3;
        const float* sdp = sd + v * 3 * NB;
        acc[0] = fmaf(w, vtp[0], acc[0]);
        acc[1] = fmaf(w, vtp[1], acc[1]);
        acc[2] = fmaf(w, vtp[2], acc[2]);
#pragma unroll
        for (int k = 0; k < 3 * NB; ++k) acc[3 + k] = fmaf(w, sdp[k], acc[3 + k]);
    }
#pragma unroll
    for (int k = 0; k < 33; ++k) {
#pragma unroll
        for (int off = 16; off > 0; off >>= 1)
            acc[k] += __shfl_xor_sync(0xffffffffu, acc[k], off);
    }
    __shared__ float sm[33];
    if (threadIdx.x < 33) sm[threadIdx.x] = 0.f;
    __syncthreads();
    if ((threadIdx.x & 31) == 0) {
#pragma unroll
        for (int k = 0; k < 33; ++k) atomicAdd(&sm[k], acc[k]);
    }
    __syncthreads();
    if (threadIdx.x < 3) g_JrT[j * 3 + threadIdx.x] = sm[threadIdx.x];
    if (threadIdx.x >= 3 && threadIdx.x < 33)
        g_JrS[j * 3 * NB + threadIdx.x - 3] = sm[threadIdx.x];
}

// ---------------------------------------------------------------------------
// Kernel B: per-batch joints, Rodrigues, kinematic chain, G, lrotmin.
// grid = B blocks, 32 threads (one warp).
// ---------------------------------------------------------------------------
__global__ __launch_bounds__(32) void kB(const float* __restrict__ betas,
                                         const float* __restrict__ thetas,
                                         const float* __restrict__ scale) {
    int b = blockIdx.x;
    int t = threadIdx.x;
    __shared__ float R[NJ][9];
    __shared__ float J[NJ][3];
    __shared__ float W[NJ][12];   // [r*4 + c], c==3 -> translation

    if (t < NJ) {
        // Joint locations J(beta)
#pragma unroll
        for (int c = 0; c < 3; ++c) {
            float s = g_JrT[t * 3 + c];
#pragma unroll
            for (int k = 0; k < NB; ++k)
                s = fmaf(g_JrS[t * 3 * NB + c * NB + k], betas[b * NB + k], s);
            J[t][c] = s;
        }
        // Rodrigues
        float x = thetas[b * NJ * 3 + t * 3 + 0];
        float y = thetas[b * NJ * 3 + t * 3 + 1];
        float z = thetas[b * NJ * 3 + t * 3 + 2];
        float th = sqrtf(x * x + y * y + z * z) + 1e-8f;
        float rx = x / th, ry = y / th, rz = z / th;
        float cth = cosf(th), sth = sinf(th), ic = 1.f - cth;
        float r[9];
        r[0] = cth + ic * rx * rx;
        r[1] = ic * rx * ry - sth * rz;
        r[2] = ic * rx * rz + sth * ry;
        r[3] = ic * rx * ry + sth * rz;
        r[4] = cth + ic * ry * ry;
        r[5] = ic * ry * rz - sth * rx;
        r[6] = ic * rx * rz - sth * ry;
        r[7] = ic * ry * rz + sth * rx;
        r[8] = cth + ic * rz * rz;
        if (t == 0) {
            float sc = scale[0];
#pragma unroll
            for (int k = 0; k < 9; ++k) r[k] *= sc;
        }
#pragma unroll
        for (int k = 0; k < 9; ++k) R[t][k] = r[k];
    }
    __syncthreads();

    if (t == 0) {
        // Root
#pragma unroll
        for (int rr = 0; rr < 3; ++rr) {
            W[0][rr * 4 + 0] = R[0][rr * 3 + 0];
            W[0][rr * 4 + 1] = R[0][rr * 3 + 1];
            W[0][rr * 4 + 2] = R[0][rr * 3 + 2];
            W[0][rr * 4 + 3] = J[0][rr];
        }
        for (int i = 1; i < NJ; ++i) {
            int p = c_par[i];
            float tx = J[i][0] - J[p][0];
            float ty = J[i][1] - J[p][1];
            float tz = J[i][2] - J[p][2];
#pragma unroll
            for (int rr = 0; rr < 3; ++rr) {
                float w0 = W[p][rr * 4 + 0], w1 = W[p][rr * 4 + 1],
                      w2 = W[p][rr * 4 + 2], w3 = W[p][rr * 4 + 3];
#pragma unroll
                for (int cc = 0; cc < 3; ++cc)
                    W[i][rr * 4 + cc] = w0 * R[i][0 * 3 + cc] +
                                        w1 * R[i][1 * 3 + cc] +
                                        w2 * R[i][2 * 3 + cc];
                W[i][rr * 4 + 3] = w0 * tx + w1 * ty + w2 * tz + w3;
            }
        }
    }
    __syncthreads();

    if (t < NJ) {
        float* g = g_G + ((size_t)b * NJ + t) * 12;
#pragma unroll
        for (int rr = 0; rr < 3; ++rr) {
            float w0 = W[t][rr * 4 + 0], w1 = W[t][rr * 4 + 1],
                  w2 = W[t][rr * 4 + 2], w3 = W[t][rr * 4 + 3];
            g[rr * 4 + 0] = w0;
            g[rr * 4 + 1] = w1;
            g[rr * 4 + 2] = w2;
            g[rr * 4 + 3] = w3 - (w0 * J[t][0] + w1 * J[t][1] + w2 * J[t][2]);
        }
    }
    // lrotmin (excludes root, unaffected by scale)
    for (int idx = t; idx < NP; idx += 32) {
        int j = idx / 9 + 1;
        int rc = idx % 9;
        float v = R[j][rc];
        if (rc == 0 || rc == 4 || rc == 8) v -= 1.f;
        g_lrot[(size_t)b * NP + idx] = v;
    }
}

// ---------------------------------------------------------------------------
// Kernel C: fused shape blend + pose blend + LBS + translation.
// grid = (ceil(NVERT/256), ceil(B/TB)), 256 threads. Thread = 1 vertex x TB batches.
// ---------------------------------------------------------------------------
__global__ __launch_bounds__(256) void kC(const float* __restrict__ vt,
                                          const float* __restrict__ sd,
                                          const float* __restrict__ pd,
                                          const float* __restrict__ wgt,
                                          const float* __restrict__ betas,
                                          const float* __restrict__ trans,
                                          float* __restrict__ out, int Btot) {
    __shared__ __align__(16) float lr_sh[NP][TB];
    __shared__ __align__(16) float G_sh[TB][NJ][12];
    __shared__ __align__(16) float bet_sh[NB][TB];
    __shared__ float tr_sh[TB][3];

    int b0 = blockIdx.y * TB;
    int bcnt = Btot - b0; if (bcnt > TB) bcnt = TB;

    for (int i = threadIdx.x; i < NP * TB; i += 256) {
        int p = i / TB, bb = i % TB;
        lr_sh[p][bb] = (bb < bcnt) ? g_lrot[(size_t)(b0 + bb) * NP + p] : 0.f;
    }
    for (int i = threadIdx.x; i < TB * NJ * 12; i += 256) {
        int bb = i / (NJ * 12), k = i % (NJ * 12);
        G_sh[bb][k / 12][k % 12] =
            (bb < bcnt) ? g_G[(size_t)(b0 + bb) * NJ * 12 + k] : 0.f;
    }
    for (int i = threadIdx.x; i < NB * TB; i += 256) {
        int s = i / TB, bb = i % TB;
        bet_sh[s][bb] = (bb < bcnt) ? betas[(b0 + bb) * NB + s] : 0.f;
    }
    for (int i = threadIdx.x; i < TB * 3; i += 256) {
        int bb = i / 3, c = i % 3;
        tr_sh[bb][c] = (bb < bcnt) ? trans[(b0 + bb) * 3 + c] : 0.f;
    }
    __syncthreads();

    int v = blockIdx.x * 256 + threadIdx.x;
    if (v >= NVERT) return;

    float acc0[TB], acc1[TB], acc2[TB];
#pragma unroll
    for (int q = 0; q < TB; ++q) { acc0[q] = 0.f; acc1[q] = 0.f; acc2[q] = 0.f; }

    // Pose blend: 207-term dot per coord, TB batches at a time
    const float* pdv = pd + (size_t)v * 3 * NP;
    for (int p = 0; p < NP; ++p) {
        float pa = __ldg(pdv + p);
        float pb = __ldg(pdv + NP + p);
        float pc = __ldg(pdv + 2 * NP + p);
        const float4* l4 = reinterpret_cast<const float4*>(lr_sh[p]);
#pragma unroll
        for (int q = 0; q < TB / 4; ++q) {
            float4 l = l4[q];
            acc0[4*q+0] = fmaf(pa, l.x, acc0[4*q+0]);
            acc0[4*q+1] = fmaf(pa, l.y, acc0[4*q+1]);
            acc0[4*q+2] = fmaf(pa, l.z, acc0[4*q+2]);
            acc0[4*q+3] = fmaf(pa, l.w, acc0[4*q+3]);
            acc1[4*q+0] = fmaf(pb, l.x, acc1[4*q+0]);
            acc1[4*q+1] = fmaf(pb, l.y, acc1[4*q+1]);
            acc1[4*q+2] = fmaf(pb, l.z, acc1[4*q+2]);
            acc1[4*q+3] = fmaf(pb, l.w, acc1[4*q+3]);
            acc2[4*q+0] = fmaf(pc, l.x, acc2[4*q+0]);
            acc2[4*q+1] = fmaf(pc, l.y, acc2[4*q+1]);
            acc2[4*q+2] = fmaf(pc, l.z, acc2[4*q+2]);
            acc2[4*q+3] = fmaf(pc, l.w, acc2[4*q+3]);
        }
    }
    // Shape blend: 10-term dot
    const float* sdv = sd + (size_t)v * 3 * NB;
#pragma unroll
    for (int s = 0; s < NB; ++s) {
        float sa = sdv[s];
        float sb = sdv[NB + s];
        float sc = sdv[2 * NB + s];
        const float4* b4 = reinterpret_cast<const float4*>(bet_sh[s]);
#pragma unroll
        for (int q = 0; q < TB / 4; ++q) {
            float4 l = b4[q];
            acc0[4*q+0] = fmaf(sa, l.x, acc0[4*q+0]);
            acc0[4*q+1] = fmaf(sa, l.y, acc0[4*q+1]);
            acc0[4*q+2] = fmaf(sa, l.z, acc0[4*q+2]);
            acc0[4*q+3] = fmaf(sa, l.w, acc0[4*q+3]);
            acc1[4*q+0] = fmaf(sb, l.x, acc1[4*q+0]);
            acc1[4*q+1] = fmaf(sb, l.y, acc1[4*q+1]);
            acc1[4*q+2] = fmaf(sb, l.z, acc1[4*q+2]);
            acc1[4*q+3] = fmaf(sb, l.w, acc1[4*q+3]);
            acc2[4*q+0] = fmaf(sc, l.x, acc2[4*q+0]);
            acc2[4*q+1] = fmaf(sc, l.y, acc2[4*q+1]);
            acc2[4*q+2] = fmaf(sc, l.z, acc2[4*q+2]);
            acc2[4*q+3] = fmaf(sc, l.w, acc2[4*q+3]);
        }
    }

    float vt0 = vt[v * 3 + 0], vt1 = vt[v * 3 + 1], vt2 = vt[v * 3 + 2];
    float wv[NJ];
#pragma unroll
    for (int j = 0; j < NJ; ++j) wv[j] = wgt[v * NJ + j];

    for (int bb = 0; bb < bcnt; ++bb) {
        float px = vt0 + acc0[bb];
        float py = vt1 + acc1[bb];
        float pz = vt2 + acc2[bb];
        float ox = 0.f, oy = 0.f, oz = 0.f;
#pragma unroll
        for (int j = 0; j < NJ; ++j) {
            const float4* g = reinterpret_cast<const float4*>(G_sh[bb][j]);
            float4 g0 = g[0], g1 = g[1], g2 = g[2];
            float w = wv[j];
            ox = fmaf(w, fmaf(g0.x, px, fmaf(g0.y, py, fmaf(g0.z, pz, g0.w))), ox);
            oy = fmaf(w, fmaf(g1.x, px, fmaf(g1.y, py, fmaf(g1.z, pz, g1.w))), oy);
            oz = fmaf(w, fmaf(g2.x, px, fmaf(g2.y, py, fmaf(g2.z, pz, g2.w))), oz);
        }
        size_t o = ((size_t)(b0 + bb) * NVERT + v) * 3;
        out[o + 0] = ox + tr_sh[bb][0];
        out[o + 1] = oy + tr_sh[bb][1];
        out[o + 2] = oz + tr_sh[bb][2];
    }
}

// ---------------------------------------------------------------------------
// Kernel D: joints = J_regressor @ result. grid = B blocks, 256 threads.
// ---------------------------------------------------------------------------
__global__ __launch_bounds__(256) void kD(const float* __restrict__ Jr,
                                          const float* __restrict__ result,
                                          float* __restrict__ joints) {
    int b = blockIdx.x;
    float acc[NJ][3];
#pragma unroll
    for (int j = 0; j < NJ; ++j) { acc[j][0] = 0.f; acc[j][1] = 0.f; acc[j][2] = 0.f; }

    const float* rb = result + (size_t)b * NVERT * 3;
    for (int v = threadIdx.x; v < NVERT; v += 256) {
        float rx = rb[v * 3 + 0], ry = rb[v * 3 + 1], rz = rb[v * 3 + 2];
#pragma unroll
        for (int j = 0; j < NJ; ++j) {
            float w = __ldg(&Jr[j * NVERT + v]);
            acc[j][0] = fmaf(w, rx, acc[j][0]);
            acc[j][1] = fmaf(w, ry, acc[j][1]);
            acc[j][2] = fmaf(w, rz, acc[j][2]);
        }
    }
    __shared__ float sm[NJ * 3];
    if (threadIdx.x < NJ * 3) sm[threadIdx.x] = 0.f;
    __syncthreads();
#pragma unroll
    for (int j = 0; j < NJ; ++j) {
#pragma unroll
        for (int c = 0; c < 3; ++c) {
            float x = acc[j][c];
#pragma unroll
            for (int off = 16; off > 0; off >>= 1)
                x += __shfl_xor_sync(0xffffffffu, x, off);
            if ((threadIdx.x & 31) == 0) atomicAdd(&sm[j * 3 + c], x);
        }
    }
    __syncthreads();
    if (threadIdx.x < NJ * 3) joints[(size_t)b * NJ * 3 + threadIdx.x] = sm[threadIdx.x];
}

// ---------------------------------------------------------------------------
extern "C" void kernel_launch(void* const* d_in, const int* in_sizes, int n_in,
                              void* d_out, int out_size) {
    const float* betas  = (const float*)d_in[0];
    const float* thetas = (const float*)d_in[1];
    const float* trans  = (const float*)d_in[2];
    const float* scale  = (const float*)d_in[3];
    const float* vt     = (const float*)d_in[4];
    const float* sd     = (const float*)d_in[5];
    const float* pd     = (const float*)d_in[6];
    const float* Jr     = (const float*)d_in[7];
    const float* wgt    = (const float*)d_in[8];

    int Btot = in_sizes[0] / NB;
    float* out = (float*)d_out;
    float* joints = out + (size_t)Btot * NVERT * 3;

    kA<<<NJ, 256>>>(Jr, vt, sd);
    kB<<<Btot, 32>>>(betas, thetas, scale);
    dim3 gc((NVERT + 255) / 256, (Btot + TB - 1) / TB);
    kC<<<gc, 256>>>(vt, sd, pd, wgt, betas, trans, out, Btot);
    kD<<<Btot, 256>>>(Jr, out, joints);
}

// round 2
// speedup vs baseline: 1.0293x; 1.0293x over previous
#include <cuda_runtime.h>

#define NVERT 6890
#define NJ 24
#define NB 10
#define NP 207
#define MAXB 1024
#define TB 16
#define TBH 8
#define CBLK 128
#define VSPL 8
#define VCH 862   // ceil(6890/8)

typedef unsigned long long u64;

__device__ __forceinline__ u64 pack2(float x) {
    u64 r; asm("mov.b64 %0,{%1,%1};" : "=l"(r) : "f"(x)); return r;
}
__device__ __forceinline__ void unpack2(u64 v, float& a, float& b) {
    asm("mov.b64 {%0,%1},%2;" : "=f"(a), "=f"(b) : "l"(v));
}
__device__ __forceinline__ u64 fma2(u64 a, u64 b, u64 c) {
    u64 d; asm("fma.rn.f32x2 %0,%1,%2,%3;" : "=l"(d) : "l"(a), "l"(b), "l"(c)); return d;
}
__device__ __forceinline__ u64 add2(u64 a, u64 b) {
    u64 d; asm("add.rn.f32x2 %0,%1,%2;" : "=l"(d) : "l"(a), "l"(b)); return d;
}

__constant__ int c_par[NJ] = {-1, 0, 0, 0, 1, 2, 3, 4, 5, 6, 7, 8, 9, 9, 9,
                              12, 13, 14, 16, 17, 18, 19, 20, 21};

__device__ float g_JrT[NJ * 3];
__device__ float g_JrS[NJ * 3 * NB];
__device__ float g_G[MAXB * NJ * 12];
__device__ float g_lrot[MAXB * NP];

// ---------------------------------------------------------------------------
// Kernel A: fold J_regressor into v_template and shapedirs.
// ---------------------------------------------------------------------------
__global__ __launch_bounds__(256) void kA(const float* __restrict__ Jr,
                                          const float* __restrict__ vt,
                                          const float* __restrict__ sd) {
    int j = blockIdx.x;
    float acc[33];
#pragma unroll
    for (int k = 0; k < 33; ++k) acc[k] = 0.f;

    for (int v = threadIdx.x; v < NVERT; v += blockDim.x) {
        float w = Jr[j * NVERT + v];
        const float* vtp = vt + v * 3;
        const float* sdp = sd + v * 3 * NB;
        acc[0] = fmaf(w, vtp[0], acc[0]);
        acc[1] = fmaf(w, vtp[1], acc[1]);
        acc[2] = fmaf(w, vtp[2], acc[2]);
#pragma unroll
        for (int k = 0; k < 3 * NB; ++k) acc[3 + k] = fmaf(w, sdp[k], acc[3 + k]);
    }
#pragma unroll
    for (int k = 0; k < 33; ++k) {
#pragma unroll
        for (int off = 16; off > 0; off >>= 1)
            acc[k] += __shfl_xor_sync(0xffffffffu, acc[k], off);
    }
    __shared__ float sm[33];
    if (threadIdx.x < 33) sm[threadIdx.x] = 0.f;
    __syncthreads();
    if ((threadIdx.x & 31) == 0) {
#pragma unroll
        for (int k = 0; k < 33; ++k) atomicAdd(&sm[k], acc[k]);
    }
    __syncthreads();
    if (threadIdx.x < 3) g_JrT[j * 3 + threadIdx.x] = sm[threadIdx.x];
    if (threadIdx.x >= 3 && threadIdx.x < 33)
        g_JrS[j * 3 * NB + threadIdx.x - 3] = sm[threadIdx.x];
}

// ---------------------------------------------------------------------------
// Kernel B: per-batch joints, Rodrigues, kinematic chain, G, lrotmin.
// ---------------------------------------------------------------------------
__global__ __launch_bounds__(32) void kB(const float* __restrict__ betas,
                                         const float* __restrict__ thetas,
                                         const float* __restrict__ scale) {
    int b = blockIdx.x;
    int t = threadIdx.x;
    __shared__ float R[NJ][9];
    __shared__ float J[NJ][3];
    __shared__ float W[NJ][12];

    if (t < NJ) {
#pragma unroll
        for (int c = 0; c < 3; ++c) {
            float s = g_JrT[t * 3 + c];
#pragma unroll
            for (int k = 0; k < NB; ++k)
                s = fmaf(g_JrS[t * 3 * NB + c * NB + k], betas[b * NB + k], s);
            J[t][c] = s;
        }
        float x = thetas[b * NJ * 3 + t * 3 + 0];
        float y = thetas[b * NJ * 3 + t * 3 + 1];
        float z = thetas[b * NJ * 3 + t * 3 + 2];
        float th = sqrtf(x * x + y * y + z * z) + 1e-8f;
        float rx = x / th, ry = y / th, rz = z / th;
        float cth = cosf(th), sth = sinf(th), ic = 1.f - cth;
        float r[9];
        r[0] = cth + ic * rx * rx;
        r[1] = ic * rx * ry - sth * rz;
        r[2] = ic * rx * rz + sth * ry;
        r[3] = ic * rx * ry + sth * rz;
        r[4] = cth + ic * ry * ry;
        r[5] = ic * ry * rz - sth * rx;
        r[6] = ic * rx * rz - sth * ry;
        r[7] = ic * ry * rz + sth * rx;
        r[8] = cth + ic * rz * rz;
        if (t == 0) {
            float sc = scale[0];
#pragma unroll
            for (int k = 0; k < 9; ++k) r[k] *= sc;
        }
#pragma unroll
        for (int k = 0; k < 9; ++k) R[t][k] = r[k];
    }
    __syncthreads();

    if (t == 0) {
#pragma unroll
        for (int rr = 0; rr < 3; ++rr) {
            W[0][rr * 4 + 0] = R[0][rr * 3 + 0];
            W[0][rr * 4 + 1] = R[0][rr * 3 + 1];
            W[0][rr * 4 + 2] = R[0][rr * 3 + 2];
            W[0][rr * 4 + 3] = J[0][rr];
        }
        for (int i = 1; i < NJ; ++i) {
            int p = c_par[i];
            float tx = J[i][0] - J[p][0];
            float ty = J[i][1] - J[p][1];
            float tz = J[i][2] - J[p][2];
#pragma unroll
            for (int rr = 0; rr < 3; ++rr) {
                float w0 = W[p][rr * 4 + 0], w1 = W[p][rr * 4 + 1],
                      w2 = W[p][rr * 4 + 2], w3 = W[p][rr * 4 + 3];
#pragma unroll
                for (int cc = 0; cc < 3; ++cc)
                    W[i][rr * 4 + cc] = w0 * R[i][0 * 3 + cc] +
                                        w1 * R[i][1 * 3 + cc] +
                                        w2 * R[i][2 * 3 + cc];
                W[i][rr * 4 + 3] = w0 * tx + w1 * ty + w2 * tz + w3;
            }
        }
    }
    __syncthreads();

    if (t < NJ) {
        float* g = g_G + ((size_t)b * NJ + t) * 12;
#pragma unroll
        for (int rr = 0; rr < 3; ++rr) {
            float w0 = W[t][rr * 4 + 0], w1 = W[t][rr * 4 + 1],
                  w2 = W[t][rr * 4 + 2], w3 = W[t][rr * 4 + 3];
            g[rr * 4 + 0] = w0;
            g[rr * 4 + 1] = w1;
            g[rr * 4 + 2] = w2;
            g[rr * 4 + 3] = w3 - (w0 * J[t][0] + w1 * J[t][1] + w2 * J[t][2]);
        }
    }
    for (int idx = t; idx < NP; idx += 32) {
        int j = idx / 9 + 1;
        int rc = idx % 9;
        float v = R[j][rc];
        if (rc == 0 || rc == 4 || rc == 8) v -= 1.f;
        g_lrot[(size_t)b * NP + idx] = v;
    }
}

// ---------------------------------------------------------------------------
// Kernel C: fused shape+pose blend + LBS, fully in packed f32x2 over batch
// pairs. Thread = 1 vertex x 16 batches (8 pairs).
// ---------------------------------------------------------------------------
__global__ __launch_bounds__(CBLK) void kC(const float* __restrict__ vt,
                                           const float* __restrict__ sd,
                                           const float* __restrict__ pd,
                                           const float* __restrict__ wgt,
                                           const float* __restrict__ betas,
                                           const float* __restrict__ trans,
                                           float* __restrict__ out, int Btot) {
    __shared__ __align__(16) float lr_sh[NP][TB];
    __shared__ __align__(16) float2 G2[TBH][NJ][12];   // (even,odd) batch pairs
    __shared__ __align__(16) float bet_sh[NB][TB];
    __shared__ __align__(16) float2 tr2[TBH][3];

    int b0 = blockIdx.y * TB;
    int bcnt = Btot - b0; if (bcnt > TB) bcnt = TB;

    for (int i = threadIdx.x; i < NP * TB; i += CBLK) {
        int p = i / TB, bb = i % TB;
        lr_sh[p][bb] = (bb < bcnt) ? g_lrot[(size_t)(b0 + bb) * NP + p] : 0.f;
    }
    for (int i = threadIdx.x; i < TBH * NJ * 12; i += CBLK) {
        int q = i / (NJ * 12), k = i % (NJ * 12);
        int be = 2 * q, bo = 2 * q + 1;
        float ge = (be < bcnt) ? g_G[(size_t)(b0 + be) * NJ * 12 + k] : 0.f;
        float go = (bo < bcnt) ? g_G[(size_t)(b0 + bo) * NJ * 12 + k] : 0.f;
        G2[q][k / 12][k % 12] = make_float2(ge, go);
    }
    for (int i = threadIdx.x; i < NB * TB; i += CBLK) {
        int s = i / TB, bb = i % TB;
        bet_sh[s][bb] = (bb < bcnt) ? betas[(b0 + bb) * NB + s] : 0.f;
    }
    for (int i = threadIdx.x; i < TBH * 3; i += CBLK) {
        int q = i / 3, c = i % 3;
        int be = 2 * q, bo = 2 * q + 1;
        float te = (be < bcnt) ? trans[(b0 + be) * 3 + c] : 0.f;
        float to = (bo < bcnt) ? trans[(b0 + bo) * 3 + c] : 0.f;
        tr2[q][c] = make_float2(te, to);
    }
    __syncthreads();

    int v = blockIdx.x * CBLK + threadIdx.x;
    if (v >= NVERT) return;

    u64 A0[TBH], A1[TBH], A2[TBH];
#pragma unroll
    for (int q = 0; q < TBH; ++q) { A0[q] = 0ull; A1[q] = 0ull; A2[q] = 0ull; }

    // Pose blend: 207 terms, batch pairs packed
    const float* pdv = pd + (size_t)v * 3 * NP;
    for (int p = 0; p < NP; ++p) {
        u64 pa = pack2(__ldg(pdv + p));
        u64 pb = pack2(__ldg(pdv + NP + p));
        u64 pc = pack2(__ldg(pdv + 2 * NP + p));
        const u64* l = reinterpret_cast<const u64*>(lr_sh[p]);
#pragma unroll
        for (int q = 0; q < TBH; ++q) {
            u64 lv = l[q];
            A0[q] = fma2(pa, lv, A0[q]);
            A1[q] = fma2(pb, lv, A1[q]);
            A2[q] = fma2(pc, lv, A2[q]);
        }
    }
    // Shape blend
    const float* sdv = sd + (size_t)v * 3 * NB;
#pragma unroll
    for (int s = 0; s < NB; ++s) {
        u64 sa = pack2(sdv[s]);
        u64 sb = pack2(sdv[NB + s]);
        u64 sc = pack2(sdv[2 * NB + s]);
        const u64* l = reinterpret_cast<const u64*>(bet_sh[s]);
#pragma unroll
        for (int q = 0; q < TBH; ++q) {
            u64 lv = l[q];
            A0[q] = fma2(sa, lv, A0[q]);
            A1[q] = fma2(sb, lv, A1[q]);
            A2[q] = fma2(sc, lv, A2[q]);
        }
    }
    // v_posed (pair-packed): PX/PY/PZ in place of A0/A1/A2
    {
        u64 t0 = pack2(vt[v * 3 + 0]);
        u64 t1 = pack2(vt[v * 3 + 1]);
        u64 t2 = pack2(vt[v * 3 + 2]);
#pragma unroll
        for (int q = 0; q < TBH; ++q) {
            A0[q] = add2(A0[q], t0);
            A1[q] = add2(A1[q], t1);
            A2[q] = add2(A2[q], t2);
        }
    }

    // LBS in f32x2
    u64 O0[TBH], O1[TBH], O2[TBH];
#pragma unroll
    for (int q = 0; q < TBH; ++q) { O0[q] = 0ull; O1[q] = 0ull; O2[q] = 0ull; }

    for (int j = 0; j < NJ; ++j) {
        u64 wj = pack2(__ldg(&wgt[v * NJ + j]));
        const ulonglong2* g = reinterpret_cast<const ulonglong2*>(G2[0][j]);
        // stride between q slices in units of ulonglong2: NJ*12/2 = 144
#pragma unroll
        for (int q = 0; q < TBH; ++q) {
            const ulonglong2* gq = g + q * (NJ * 12 / 2);
            ulonglong2 ga = gq[0];  // m00, m01
            ulonglong2 gb = gq[1];  // m02, m03
            ulonglong2 gc = gq[2];  // m10, m11
            ulonglong2 gd = gq[3];  // m12, m13
            ulonglong2 ge = gq[4];  // m20, m21
            ulonglong2 gf = gq[5];  // m22, m23
            u64 t;
            t = fma2(ga.x, A0[q], fma2(ga.y, A1[q], fma2(gb.x, A2[q], gb.y)));
            O0[q] = fma2(wj, t, O0[q]);
            t = fma2(gc.x, A0[q], fma2(gc.y, A1[q], fma2(gd.x, A2[q], gd.y)));
            O1[q] = fma2(wj, t, O1[q]);
            t = fma2(ge.x, A0[q], fma2(ge.y, A1[q], fma2(gf.x, A2[q], gf.y)));
            O2[q] = fma2(wj, t, O2[q]);
        }
    }

    // translation + store
#pragma unroll
    for (int q = 0; q < TBH; ++q) {
        const u64* tq = reinterpret_cast<const u64*>(tr2[q]);
        O0[q] = add2(O0[q], tq[0]);
        O1[q] = add2(O1[q], tq[1]);
        O2[q] = add2(O2[q], tq[2]);
        float xe, xo, ye, yo, ze, zo;
        unpack2(O0[q], xe, xo);
        unpack2(O1[q], ye, yo);
        unpack2(O2[q], ze, zo);
        int be = 2 * q, bo = 2 * q + 1;
        if (be < bcnt) {
            size_t o = ((size_t)(b0 + be) * NVERT + v) * 3;
            out[o + 0] = xe; out[o + 1] = ye; out[o + 2] = ze;
        }
        if (bo < bcnt) {
            size_t o = ((size_t)(b0 + bo) * NVERT + v) * 3;
            out[o + 0] = xo; out[o + 1] = yo; out[o + 2] = zo;
        }
    }
}

// ---------------------------------------------------------------------------
// Kernel Z: zero the joints region.
// ---------------------------------------------------------------------------
__global__ __launch_bounds__(256) void kZ(float* __restrict__ joints, int n) {
    int i = blockIdx.x * 256 + threadIdx.x;
    if (i < n) joints[i] = 0.f;
}

// ---------------------------------------------------------------------------
// Kernel D: joints = J_regressor @ result, grid (B, VSPL), atomic finish.
// ---------------------------------------------------------------------------
__global__ __launch_bounds__(256) void kD(const float* __restrict__ Jr,
                                          const float* __restrict__ result,
                                          float* __restrict__ joints) {
    int b = blockIdx.x;
    int sp = blockIdx.y;
    int v0 = sp * VCH;
    int v1 = v0 + VCH; if (v1 > NVERT) v1 = NVERT;

    float acc[NJ][3];
#pragma unroll
    for (int j = 0; j < NJ; ++j) { acc[j][0] = 0.f; acc[j][1] = 0.f; acc[j][2] = 0.f; }

    const float* rb = result + (size_t)b * NVERT * 3;
    for (int v = v0 + threadIdx.x; v < v1; v += 256) {
        float rx = rb[v * 3 + 0], ry = rb[v * 3 + 1], rz = rb[v * 3 + 2];
#pragma unroll
        for (int j = 0; j < NJ; ++j) {
            float w = __ldg(&Jr[j * NVERT + v]);
            acc[j][0] = fmaf(w, rx, acc[j][0]);
            acc[j][1] = fmaf(w, ry, acc[j][1]);
            acc[j][2] = fmaf(w, rz, acc[j][2]);
        }
    }
    __shared__ float sm[NJ * 3];
    if (threadIdx.x < NJ * 3) sm[threadIdx.x] = 0.f;
    __syncthreads();
#pragma unroll
    for (int j = 0; j < NJ; ++j) {
#pragma unroll
        for (int c = 0; c < 3; ++c) {
            float x = acc[j][c];
#pragma unroll
            for (int off = 16; off > 0; off >>= 1)
                x += __shfl_xor_sync(0xffffffffu, x, off);
            if ((threadIdx.x & 31) == 0) atomicAdd(&sm[j * 3 + c], x);
        }
    }
    __syncthreads();
    if (threadIdx.x < NJ * 3)
        atomicAdd(&joints[(size_t)b * NJ * 3 + threadIdx.x], sm[threadIdx.x]);
}

// ---------------------------------------------------------------------------
extern "C" void kernel_launch(void* const* d_in, const int* in_sizes, int n_in,
                              void* d_out, int out_size) {
    const float* betas  = (const float*)d_in[0];
    const float* thetas = (const float*)d_in[1];
    const float* trans  = (const float*)d_in[2];
    const float* scale  = (const float*)d_in[3];
    const float* vt     = (const float*)d_in[4];
    const float* sd     = (const float*)d_in[5];
    const float* pd     = (const float*)d_in[6];
    const float* Jr     = (const float*)d_in[7];
    const float* wgt    = (const float*)d_in[8];

    int Btot = in_sizes[0] / NB;
    float* out = (float*)d_out;
    float* joints = out + (size_t)Btot * NVERT * 3;

    kA<<<NJ, 256>>>(Jr, vt, sd);
    kB<<<Btot, 32>>>(betas, thetas, scale);
    int nj = Btot * NJ * 3;
    kZ<<<(nj + 255) / 256, 256>>>(joints, nj);
    dim3 gc((NVERT + CBLK - 1) / CBLK, (Btot + TB - 1) / TB);
    kC<<<gc, CBLK>>>(vt, sd, pd, wgt, betas, trans, out, Btot);
    dim3 gd(Btot, VSPL);
    kD<<<gd, 256>>>(Jr, out, joints);
}

// round 3
// speedup vs baseline: 1.1356x; 1.1033x over previous
#include <cuda_runtime.h>

#define NVERT 6890
#define NJ 24
#define NB 10
#define NP 207
#define MAXB 1024
#define TB 16
#define TBH 8
#define CBLK 128
#define VSPL 8
#define VCH 862   // ceil(6890/8)

typedef unsigned long long u64;

__device__ __forceinline__ u64 pack2(float x) {
    u64 r; asm("mov.b64 %0,{%1,%1};" : "=l"(r) : "f"(x)); return r;
}
__device__ __forceinline__ void unpack2(u64 v, float& a, float& b) {
    asm("mov.b64 {%0,%1},%2;" : "=f"(a), "=f"(b) : "l"(v));
}
__device__ __forceinline__ u64 fma2(u64 a, u64 b, u64 c) {
    u64 d; asm("fma.rn.f32x2 %0,%1,%2,%3;" : "=l"(d) : "l"(a), "l"(b), "l"(c)); return d;
}
__device__ __forceinline__ u64 add2(u64 a, u64 b) {
    u64 d; asm("add.rn.f32x2 %0,%1,%2;" : "=l"(d) : "l"(a), "l"(b)); return d;
}

__constant__ int c_par[NJ] = {-1, 0, 0, 0, 1, 2, 3, 4, 5, 6, 7, 8, 9, 9, 9,
                              12, 13, 14, 16, 17, 18, 19, 20, 21};

__device__ float g_JrT[NJ * 3];
__device__ float g_JrS[NJ * 3 * NB];
__device__ float g_G[MAXB * NJ * 12];
__device__ float g_lrot[MAXB * NP];

// Transposed constant tensors: [k][v] layouts (coalesced over v)
__device__ float g_pdT[3 * NP * NVERT];   // [c*NP + p][v]  (~17 MB)
__device__ float g_sdT[3 * NB * NVERT];   // [c*NB + s][v]
__device__ float g_wT[NJ * NVERT];        // [j][v]
__device__ float g_vtT[3 * NVERT];        // [c][v]

// ---------------------------------------------------------------------------
// kTpd: tiled transpose pd[v][c][p] -> g_pdT[(c*NP+p)*NVERT + v]
// ---------------------------------------------------------------------------
__global__ __launch_bounds__(256) void kTpd(const float* __restrict__ pd) {
    __shared__ float tile[32][33];
    int c = blockIdx.z;
    int p0 = blockIdx.x * 32, v0 = blockIdx.y * 32;
    for (int r = threadIdx.y; r < 32; r += 8) {
        int v = v0 + r, p = p0 + threadIdx.x;
        tile[r][threadIdx.x] =
            (v < NVERT && p < NP) ? pd[((size_t)v * 3 + c) * NP + p] : 0.f;
    }
    __syncthreads();
    for (int r = threadIdx.y; r < 32; r += 8) {
        int p = p0 + r, v = v0 + threadIdx.x;
        if (p < NP && v < NVERT)
            g_pdT[((size_t)c * NP + p) * NVERT + v] = tile[threadIdx.x][r];
    }
}

// ---------------------------------------------------------------------------
// kT2: generic small transpose in[v*K + k] -> out[k*NVERT + v], K <= 32
// ---------------------------------------------------------------------------
__global__ __launch_bounds__(256) void kT2(const float* __restrict__ in,
                                           float* __restrict__ out, int K) {
    __shared__ float tile[32][33];
    int v0 = blockIdx.x * 32;
    for (int r = threadIdx.y; r < 32; r += 8) {
        int v = v0 + r, k = threadIdx.x;
        tile[r][k] = (v < NVERT && k < K) ? in[(size_t)v * K + k] : 0.f;
    }
    __syncthreads();
    for (int r = threadIdx.y; r < 32; r += 8) {
        int k = r, v = v0 + threadIdx.x;
        if (k < K && v < NVERT) out[(size_t)k * NVERT + v] = tile[threadIdx.x][r];
    }
}

// ---------------------------------------------------------------------------
// Kernel A: fold J_regressor into v_template and shapedirs.
// ---------------------------------------------------------------------------
__global__ __launch_bounds__(256) void kA(const float* __restrict__ Jr,
                                          const float* __restrict__ vt,
                                          const float* __restrict__ sd) {
    int j = blockIdx.x;
    float acc[33];
#pragma unroll
    for (int k = 0; k < 33; ++k) acc[k] = 0.f;

    for (int v = threadIdx.x; v < NVERT; v += blockDim.x) {
        float w = Jr[j * NVERT + v];
        const float* vtp = vt + v * 3;
        const float* sdp = sd + v * 3 * NB;
        acc[0] = fmaf(w, vtp[0], acc[0]);
        acc[1] = fmaf(w, vtp[1], acc[1]);
        acc[2] = fmaf(w, vtp[2], acc[2]);
#pragma unroll
        for (int k = 0; k < 3 * NB; ++k) acc[3 + k] = fmaf(w, sdp[k], acc[3 + k]);
    }
#pragma unroll
    for (int k = 0; k < 33; ++k) {
#pragma unroll
        for (int off = 16; off > 0; off >>= 1)
            acc[k] += __shfl_xor_sync(0xffffffffu, acc[k], off);
    }
    __shared__ float sm[33];
    if (threadIdx.x < 33) sm[threadIdx.x] = 0.f;
    __syncthreads();
    if ((threadIdx.x & 31) == 0) {
#pragma unroll
        for (int k = 0; k < 33; ++k) atomicAdd(&sm[k], acc[k]);
    }
    __syncthreads();
    if (threadIdx.x < 3) g_JrT[j * 3 + threadIdx.x] = sm[threadIdx.x];
    if (threadIdx.x >= 3 && threadIdx.x < 33)
        g_JrS[j * 3 * NB + threadIdx.x - 3] = sm[threadIdx.x];
}

// ---------------------------------------------------------------------------
// Kernel B: per-batch joints, Rodrigues, kinematic chain, G, lrotmin.
// ---------------------------------------------------------------------------
__global__ __launch_bounds__(32) void kB(const float* __restrict__ betas,
                                         const float* __restrict__ thetas,
                                         const float* __restrict__ scale) {
    int b = blockIdx.x;
    int t = threadIdx.x;
    __shared__ float R[NJ][9];
    __shared__ float J[NJ][3];
    __shared__ float W[NJ][12];

    if (t < NJ) {
#pragma unroll
        for (int c = 0; c < 3; ++c) {
            float s = g_JrT[t * 3 + c];
#pragma unroll
            for (int k = 0; k < NB; ++k)
                s = fmaf(g_JrS[t * 3 * NB + c * NB + k], betas[b * NB + k], s);
            J[t][c] = s;
        }
        float x = thetas[b * NJ * 3 + t * 3 + 0];
        float y = thetas[b * NJ * 3 + t * 3 + 1];
        float z = thetas[b * NJ * 3 + t * 3 + 2];
        float th = sqrtf(x * x + y * y + z * z) + 1e-8f;
        float rx = x / th, ry = y / th, rz = z / th;
        float cth = cosf(th), sth = sinf(th), ic = 1.f - cth;
        float r[9];
        r[0] = cth + ic * rx * rx;
        r[1] = ic * rx * ry - sth * rz;
        r[2] = ic * rx * rz + sth * ry;
        r[3] = ic * rx * ry + sth * rz;
        r[4] = cth + ic * ry * ry;
        r[5] = ic * ry * rz - sth * rx;
        r[6] = ic * rx * rz - sth * ry;
        r[7] = ic * ry * rz + sth * rx;
        r[8] = cth + ic * rz * rz;
        if (t == 0) {
            float sc = scale[0];
#pragma unroll
            for (int k = 0; k < 9; ++k) r[k] *= sc;
        }
#pragma unroll
        for (int k = 0; k < 9; ++k) R[t][k] = r[k];
    }
    __syncthreads();

    if (t == 0) {
#pragma unroll
        for (int rr = 0; rr < 3; ++rr) {
            W[0][rr * 4 + 0] = R[0][rr * 3 + 0];
            W[0][rr * 4 + 1] = R[0][rr * 3 + 1];
            W[0][rr * 4 + 2] = R[0][rr * 3 + 2];
            W[0][rr * 4 + 3] = J[0][rr];
        }
        for (int i = 1; i < NJ; ++i) {
            int p = c_par[i];
            float tx = J[i][0] - J[p][0];
            float ty = J[i][1] - J[p][1];
            float tz = J[i][2] - J[p][2];
#pragma unroll
            for (int rr = 0; rr < 3; ++rr) {
                float w0 = W[p][rr * 4 + 0], w1 = W[p][rr * 4 + 1],
                      w2 = W[p][rr * 4 + 2], w3 = W[p][rr * 4 + 3];
#pragma unroll
                for (int cc = 0; cc < 3; ++cc)
                    W[i][rr * 4 + cc] = w0 * R[i][0 * 3 + cc] +
                                        w1 * R[i][1 * 3 + cc] +
                                        w2 * R[i][2 * 3 + cc];
                W[i][rr * 4 + 3] = w0 * tx + w1 * ty + w2 * tz + w3;
            }
        }
    }
    __syncthreads();

    if (t < NJ) {
        float* g = g_G + ((size_t)b * NJ + t) * 12;
#pragma unroll
        for (int rr = 0; rr < 3; ++rr) {
            float w0 = W[t][rr * 4 + 0], w1 = W[t][rr * 4 + 1],
                  w2 = W[t][rr * 4 + 2], w3 = W[t][rr * 4 + 3];
            g[rr * 4 + 0] = w0;
            g[rr * 4 + 1] = w1;
            g[rr * 4 + 2] = w2;
            g[rr * 4 + 3] = w3 - (w0 * J[t][0] + w1 * J[t][1] + w2 * J[t][2]);
        }
    }
    for (int idx = t; idx < NP; idx += 32) {
        int j = idx / 9 + 1;
        int rc = idx % 9;
        float v = R[j][rc];
        if (rc == 0 || rc == 4 || rc == 8) v -= 1.f;
        g_lrot[(size_t)b * NP + idx] = v;
    }
}

// ---------------------------------------------------------------------------
// Kernel C: fused shape+pose blend + LBS in packed f32x2, coalesced loads.
// ---------------------------------------------------------------------------
__global__ __launch_bounds__(CBLK) void kC(const float* __restrict__ betas,
                                           const float* __restrict__ trans,
                                           float* __restrict__ out, int Btot) {
    __shared__ __align__(16) float lr_sh[NP][TB];
    __shared__ __align__(16) float2 G2[TBH][NJ][12];
    __shared__ __align__(16) float bet_sh[NB][TB];
    __shared__ __align__(16) float2 tr2[TBH][3];

    int b0 = blockIdx.y * TB;
    int bcnt = Btot - b0; if (bcnt > TB) bcnt = TB;

    for (int i = threadIdx.x; i < NP * TB; i += CBLK) {
        int p = i / TB, bb = i % TB;
        lr_sh[p][bb] = (bb < bcnt) ? g_lrot[(size_t)(b0 + bb) * NP + p] : 0.f;
    }
    for (int i = threadIdx.x; i < TBH * NJ * 12; i += CBLK) {
        int q = i / (NJ * 12), k = i % (NJ * 12);
        int be = 2 * q, bo = 2 * q + 1;
        float ge = (be < bcnt) ? g_G[(size_t)(b0 + be) * NJ * 12 + k] : 0.f;
        float go = (bo < bcnt) ? g_G[(size_t)(b0 + bo) * NJ * 12 + k] : 0.f;
        G2[q][k / 12][k % 12] = make_float2(ge, go);
    }
    for (int i = threadIdx.x; i < NB * TB; i += CBLK) {
        int s = i / TB, bb = i % TB;
        bet_sh[s][bb] = (bb < bcnt) ? betas[(b0 + bb) * NB + s] : 0.f;
    }
    for (int i = threadIdx.x; i < TBH * 3; i += CBLK) {
        int q = i / 3, c = i % 3;
        int be = 2 * q, bo = 2 * q + 1;
        float te = (be < bcnt) ? trans[(b0 + be) * 3 + c] : 0.f;
        float to = (bo < bcnt) ? trans[(b0 + bo) * 3 + c] : 0.f;
        tr2[q][c] = make_float2(te, to);
    }
    __syncthreads();

    int v = blockIdx.x * CBLK + threadIdx.x;
    if (v >= NVERT) return;

    u64 A0[TBH], A1[TBH], A2[TBH];
#pragma unroll
    for (int q = 0; q < TBH; ++q) { A0[q] = 0ull; A1[q] = 0ull; A2[q] = 0ull; }

    // Pose blend: coalesced loads from g_pdT[c][p][v]
    const float* pb0 = g_pdT + v;
    const float* pb1 = g_pdT + (size_t)NP * NVERT + v;
    const float* pb2 = g_pdT + (size_t)2 * NP * NVERT + v;
#pragma unroll 2
    for (int p = 0; p < NP; ++p) {
        u64 pa = pack2(__ldg(pb0 + (size_t)p * NVERT));
        u64 pbv = pack2(__ldg(pb1 + (size_t)p * NVERT));
        u64 pc = pack2(__ldg(pb2 + (size_t)p * NVERT));
        const ulonglong2* l = reinterpret_cast<const ulonglong2*>(lr_sh[p]);
#pragma unroll
        for (int h = 0; h < TBH / 2; ++h) {
            ulonglong2 lv = l[h];
            A0[2*h]   = fma2(pa,  lv.x, A0[2*h]);
            A0[2*h+1] = fma2(pa,  lv.y, A0[2*h+1]);
            A1[2*h]   = fma2(pbv, lv.x, A1[2*h]);
            A1[2*h+1] = fma2(pbv, lv.y, A1[2*h+1]);
            A2[2*h]   = fma2(pc,  lv.x, A2[2*h]);
            A2[2*h+1] = fma2(pc,  lv.y, A2[2*h+1]);
        }
    }
    // Shape blend (g_sdT[c*NB+s][v])
#pragma unroll
    for (int s = 0; s < NB; ++s) {
        u64 sa = pack2(__ldg(&g_sdT[(size_t)(0 * NB + s) * NVERT + v]));
        u64 sb = pack2(__ldg(&g_sdT[(size_t)(1 * NB + s) * NVERT + v]));
        u64 sc = pack2(__ldg(&g_sdT[(size_t)(2 * NB + s) * NVERT + v]));
        const ulonglong2* l = reinterpret_cast<const ulonglong2*>(bet_sh[s]);
#pragma unroll
        for (int h = 0; h < TBH / 2; ++h) {
            ulonglong2 lv = l[h];
            A0[2*h]   = fma2(sa, lv.x, A0[2*h]);
            A0[2*h+1] = fma2(sa, lv.y, A0[2*h+1]);
            A1[2*h]   = fma2(sb, lv.x, A1[2*h]);
            A1[2*h+1] = fma2(sb, lv.y, A1[2*h+1]);
            A2[2*h]   = fma2(sc, lv.x, A2[2*h]);
            A2[2*h+1] = fma2(sc, lv.y, A2[2*h+1]);
        }
    }
    // v_template
    {
        u64 t0 = pack2(__ldg(&g_vtT[0 * NVERT + v]));
        u64 t1 = pack2(__ldg(&g_vtT[1 * NVERT + v]));
        u64 t2 = pack2(__ldg(&g_vtT[2 * NVERT + v]));
#pragma unroll
        for (int q = 0; q < TBH; ++q) {
            A0[q] = add2(A0[q], t0);
            A1[q] = add2(A1[q], t1);
            A2[q] = add2(A2[q], t2);
        }
    }

    // LBS in f32x2 (weights coalesced from g_wT[j][v])
    u64 O0[TBH], O1[TBH], O2[TBH];
#pragma unroll
    for (int q = 0; q < TBH; ++q) { O0[q] = 0ull; O1[q] = 0ull; O2[q] = 0ull; }

    for (int j = 0; j < NJ; ++j) {
        u64 wj = pack2(__ldg(&g_wT[(size_t)j * NVERT + v]));
        const ulonglong2* g = reinterpret_cast<const ulonglong2*>(G2[0][j]);
#pragma unroll
        for (int q = 0; q < TBH; ++q) {
            const ulonglong2* gq = g + q * (NJ * 12 / 2);
            ulonglong2 ga = gq[0];
            ulonglong2 gb = gq[1];
            ulonglong2 gc = gq[2];
            ulonglong2 gd = gq[3];
            ulonglong2 ge = gq[4];
            ulonglong2 gf = gq[5];
            u64 t;
            t = fma2(ga.x, A0[q], fma2(ga.y, A1[q], fma2(gb.x, A2[q], gb.y)));
            O0[q] = fma2(wj, t, O0[q]);
            t = fma2(gc.x, A0[q], fma2(gc.y, A1[q], fma2(gd.x, A2[q], gd.y)));
            O1[q] = fma2(wj, t, O1[q]);
            t = fma2(ge.x, A0[q], fma2(ge.y, A1[q], fma2(gf.x, A2[q], gf.y)));
            O2[q] = fma2(wj, t, O2[q]);
        }
    }

#pragma unroll
    for (int q = 0; q < TBH; ++q) {
        const u64* tq = reinterpret_cast<const u64*>(tr2[q]);
        O0[q] = add2(O0[q], tq[0]);
        O1[q] = add2(O1[q], tq[1]);
        O2[q] = add2(O2[q], tq[2]);
        float xe, xo, ye, yo, ze, zo;
        unpack2(O0[q], xe, xo);
        unpack2(O1[q], ye, yo);
        unpack2(O2[q], ze, zo);
        int be = 2 * q, bo = 2 * q + 1;
        if (be < bcnt) {
            size_t o = ((size_t)(b0 + be) * NVERT + v) * 3;
            out[o + 0] = xe; out[o + 1] = ye; out[o + 2] = ze;
        }
        if (bo < bcnt) {
            size_t o = ((size_t)(b0 + bo) * NVERT + v) * 3;
            out[o + 0] = xo; out[o + 1] = yo; out[o + 2] = zo;
        }
    }
}

// ---------------------------------------------------------------------------
// Kernel Z: zero the joints region.
// ---------------------------------------------------------------------------
__global__ __launch_bounds__(256) void kZ(float* __restrict__ joints, int n) {
    int i = blockIdx.x * 256 + threadIdx.x;
    if (i < n) joints[i] = 0.f;
}

// ---------------------------------------------------------------------------
// Kernel D: joints = J_regressor @ result, grid (B, VSPL), atomic finish.
// ---------------------------------------------------------------------------
__global__ __launch_bounds__(256) void kD(const float* __restrict__ Jr,
                                          const float* __restrict__ result,
                                          float* __restrict__ joints) {
    int b = blockIdx.x;
    int sp = blockIdx.y;
    int v0 = sp * VCH;
    int v1 = v0 + VCH; if (v1 > NVERT) v1 = NVERT;

    float acc[NJ][3];
#pragma unroll
    for (int j = 0; j < NJ; ++j) { acc[j][0] = 0.f; acc[j][1] = 0.f; acc[j][2] = 0.f; }

    const float* rb = result + (size_t)b * NVERT * 3;
    for (int v = v0 + threadIdx.x; v < v1; v += 256) {
        float rx = rb[v * 3 + 0], ry = rb[v * 3 + 1], rz = rb[v * 3 + 2];
#pragma unroll
        for (int j = 0; j < NJ; ++j) {
            float w = __ldg(&Jr[j * NVERT + v]);
            acc[j][0] = fmaf(w, rx, acc[j][0]);
            acc[j][1] = fmaf(w, ry, acc[j][1]);
            acc[j][2] = fmaf(w, rz, acc[j][2]);
        }
    }
    __shared__ float sm[NJ * 3];
    if (threadIdx.x < NJ * 3) sm[threadIdx.x] = 0.f;
    __syncthreads();
#pragma unroll
    for (int j = 0; j < NJ; ++j) {
#pragma unroll
        for (int c = 0; c < 3; ++c) {
            float x = acc[j][c];
#pragma unroll
            for (int off = 16; off > 0; off >>= 1)
                x += __shfl_xor_sync(0xffffffffu, x, off);
            if ((threadIdx.x & 31) == 0) atomicAdd(&sm[j * 3 + c], x);
        }
    }
    __syncthreads();
    if (threadIdx.x < NJ * 3)
        atomicAdd(&joints[(size_t)b * NJ * 3 + threadIdx.x], sm[threadIdx.x]);
}

// ---------------------------------------------------------------------------
extern "C" void kernel_launch(void* const* d_in, const int* in_sizes, int n_in,
                              void* d_out, int out_size) {
    const float* betas  = (const float*)d_in[0];
    const float* thetas = (const float*)d_in[1];
    const float* trans  = (const float*)d_in[2];
    const float* scale  = (const float*)d_in[3];
    const float* vt     = (const float*)d_in[4];
    const float* sd     = (const float*)d_in[5];
    const float* pd     = (const float*)d_in[6];
    const float* Jr     = (const float*)d_in[7];
    const float* wgt    = (const float*)d_in[8];

    int Btot = in_sizes[0] / NB;
    float* out = (float*)d_out;
    float* joints = out + (size_t)Btot * NVERT * 3;

    // Transposes (coalesced [k][v] layouts)
    {
        float* wT; cudaGetSymbolAddress((void**)&wT, g_wT);
        float* sdT; cudaGetSymbolAddress((void**)&sdT, g_sdT);
        float* vtT; cudaGetSymbolAddress((void**)&vtT, g_vtT);
        dim3 tb(32, 8);
        dim3 gpd((NP + 31) / 32, (NVERT + 31) / 32, 3);
        kTpd<<<gpd, tb>>>(pd);
        dim3 g2((NVERT + 31) / 32, 1);
        kT2<<<g2, tb>>>(wgt, wT, NJ);
        kT2<<<g2, tb>>>(sd, sdT, 3 * NB);
        kT2<<<g2, tb>>>(vt, vtT, 3);
    }

    kA<<<NJ, 256>>>(Jr, vt, sd);
    kB<<<Btot, 32>>>(betas, thetas, scale);
    int nj = Btot * NJ * 3;
    kZ<<<(nj + 255) / 256, 256>>>(joints, nj);
    dim3 gc((NVERT + CBLK - 1) / CBLK, (Btot + TB - 1) / TB);
    kC<<<gc, CBLK>>>(betas, trans, out, Btot);
    dim3 gd(Btot, VSPL);
    kD<<<gd, 256>>>(Jr, out, joints);
}

// round 4
// speedup vs baseline: 1.2191x; 1.0736x over previous
#include <cuda_runtime.h>

#define NVERT 6890
#define NJ 24
#define NB 10
#define NP 207
#define MAXB 1024
#define TB 16
#define TBH 8
#define CBLK 128
#define VSPL 8
#define VCH 862   // ceil(6890/8)

typedef unsigned long long u64;

__device__ __forceinline__ u64 pack2(float x) {
    u64 r; asm("mov.b64 %0,{%1,%1};" : "=l"(r) : "f"(x)); return r;
}
__device__ __forceinline__ void unpack2(u64 v, float& a, float& b) {
    asm("mov.b64 {%0,%1},%2;" : "=f"(a), "=f"(b) : "l"(v));
}
__device__ __forceinline__ u64 fma2(u64 a, u64 b, u64 c) {
    u64 d; asm("fma.rn.f32x2 %0,%1,%2,%3;" : "=l"(d) : "l"(a), "l"(b), "l"(c)); return d;
}
__device__ __forceinline__ u64 add2(u64 a, u64 b) {
    u64 d; asm("add.rn.f32x2 %0,%1,%2;" : "=l"(d) : "l"(a), "l"(b)); return d;
}

__constant__ int c_par[NJ] = {-1, 0, 0, 0, 1, 2, 3, 4, 5, 6, 7, 8, 9, 9, 9,
                              12, 13, 14, 16, 17, 18, 19, 20, 21};

__device__ float g_JrT[NJ * 3];
__device__ float g_JrS[NJ * 3 * NB];
__device__ float g_G[MAXB * NJ * 12];
__device__ float g_lrot[MAXB * NP];

// Transposed constant tensors: [k][v] layouts (coalesced over v)
__device__ float g_pdT[3 * NP * NVERT];   // [c*NP + p][v]
__device__ float g_sdT[3 * NB * NVERT];   // [c*NB + s][v]
__device__ float g_wT[NJ * NVERT];        // [j][v]
__device__ float g_vtT[3 * NVERT];        // [c][v]

// ---------------------------------------------------------------------------
// kTpd: tiled transpose pd[v][c][p] -> g_pdT[(c*NP+p)*NVERT + v]
// ---------------------------------------------------------------------------
__global__ __launch_bounds__(256) void kTpd(const float* __restrict__ pd) {
    __shared__ float tile[32][33];
    int c = blockIdx.z;
    int p0 = blockIdx.x * 32, v0 = blockIdx.y * 32;
    for (int r = threadIdx.y; r < 32; r += 8) {
        int v = v0 + r, p = p0 + threadIdx.x;
        tile[r][threadIdx.x] =
            (v < NVERT && p < NP) ? pd[((size_t)v * 3 + c) * NP + p] : 0.f;
    }
    __syncthreads();
    for (int r = threadIdx.y; r < 32; r += 8) {
        int p = p0 + r, v = v0 + threadIdx.x;
        if (p < NP && v < NVERT)
            g_pdT[((size_t)c * NP + p) * NVERT + v] = tile[threadIdx.x][r];
    }
}

// ---------------------------------------------------------------------------
// kT2: generic small transpose in[v*K + k] -> out[k*NVERT + v], K <= 32
// ---------------------------------------------------------------------------
__global__ __launch_bounds__(256) void kT2(const float* __restrict__ in,
                                           float* __restrict__ out, int K) {
    __shared__ float tile[32][33];
    int v0 = blockIdx.x * 32;
    for (int r = threadIdx.y; r < 32; r += 8) {
        int v = v0 + r, k = threadIdx.x;
        tile[r][k] = (v < NVERT && k < K) ? in[(size_t)v * K + k] : 0.f;
    }
    __syncthreads();
    for (int r = threadIdx.y; r < 32; r += 8) {
        int k = r, v = v0 + threadIdx.x;
        if (k < K && v < NVERT) out[(size_t)k * NVERT + v] = tile[threadIdx.x][r];
    }
}

// ---------------------------------------------------------------------------
// Kernel A: fold J_regressor into v_template and shapedirs (coalesced reads
// from transposed layouts).
// ---------------------------------------------------------------------------
__global__ __launch_bounds__(256) void kA(const float* __restrict__ Jr) {
    int j = blockIdx.x;
    float acc[33];
#pragma unroll
    for (int k = 0; k < 33; ++k) acc[k] = 0.f;

    for (int v = threadIdx.x; v < NVERT; v += blockDim.x) {
        float w = Jr[j * NVERT + v];
#pragma unroll
        for (int c = 0; c < 3; ++c)
            acc[c] = fmaf(w, __ldg(&g_vtT[c * NVERT + v]), acc[c]);
#pragma unroll
        for (int k = 0; k < 3 * NB; ++k)
            acc[3 + k] = fmaf(w, __ldg(&g_sdT[(size_t)k * NVERT + v]), acc[3 + k]);
    }
#pragma unroll
    for (int k = 0; k < 33; ++k) {
#pragma unroll
        for (int off = 16; off > 0; off >>= 1)
            acc[k] += __shfl_xor_sync(0xffffffffu, acc[k], off);
    }
    __shared__ float sm[33];
    if (threadIdx.x < 33) sm[threadIdx.x] = 0.f;
    __syncthreads();
    if ((threadIdx.x & 31) == 0) {
#pragma unroll
        for (int k = 0; k < 33; ++k) atomicAdd(&sm[k], acc[k]);
    }
    __syncthreads();
    // g_sdT layout is [c*NB+s]; reorder into g_JrS[j][c][s]
    if (threadIdx.x < 3) g_JrT[j * 3 + threadIdx.x] = sm[threadIdx.x];
    if (threadIdx.x >= 3 && threadIdx.x < 33) {
        int k = threadIdx.x - 3;          // k = c*NB + s
        g_JrS[j * 3 * NB + k] = sm[threadIdx.x];
    }
}

// ---------------------------------------------------------------------------
// Kernel B: per-batch joints, Rodrigues, kinematic chain, G, lrotmin.
// ---------------------------------------------------------------------------
__global__ __launch_bounds__(32) void kB(const float* __restrict__ betas,
                                         const float* __restrict__ thetas,
                                         const float* __restrict__ scale) {
    int b = blockIdx.x;
    int t = threadIdx.x;
    __shared__ float R[NJ][9];
    __shared__ float J[NJ][3];
    __shared__ float W[NJ][12];

    if (t < NJ) {
#pragma unroll
        for (int c = 0; c < 3; ++c) {
            float s = g_JrT[t * 3 + c];
#pragma unroll
            for (int k = 0; k < NB; ++k)
                s = fmaf(g_JrS[t * 3 * NB + c * NB + k], betas[b * NB + k], s);
            J[t][c] = s;
        }
        float x = thetas[b * NJ * 3 + t * 3 + 0];
        float y = thetas[b * NJ * 3 + t * 3 + 1];
        float z = thetas[b * NJ * 3 + t * 3 + 2];
        float th = sqrtf(x * x + y * y + z * z) + 1e-8f;
        float rx = x / th, ry = y / th, rz = z / th;
        float cth = cosf(th), sth = sinf(th), ic = 1.f - cth;
        float r[9];
        r[0] = cth + ic * rx * rx;
        r[1] = ic * rx * ry - sth * rz;
        r[2] = ic * rx * rz + sth * ry;
        r[3] = ic * rx * ry + sth * rz;
        r[4] = cth + ic * ry * ry;
        r[5] = ic * ry * rz - sth * rx;
        r[6] = ic * rx * rz - sth * ry;
        r[7] = ic * ry * rz + sth * rx;
        r[8] = cth + ic * rz * rz;
        if (t == 0) {
            float sc = scale[0];
#pragma unroll
            for (int k = 0; k < 9; ++k) r[k] *= sc;
        }
#pragma unroll
        for (int k = 0; k < 9; ++k) R[t][k] = r[k];
    }
    __syncthreads();

    if (t == 0) {
#pragma unroll
        for (int rr = 0; rr < 3; ++rr) {
            W[0][rr * 4 + 0] = R[0][rr * 3 + 0];
            W[0][rr * 4 + 1] = R[0][rr * 3 + 1];
            W[0][rr * 4 + 2] = R[0][rr * 3 + 2];
            W[0][rr * 4 + 3] = J[0][rr];
        }
        for (int i = 1; i < NJ; ++i) {
            int p = c_par[i];
            float tx = J[i][0] - J[p][0];
            float ty = J[i][1] - J[p][1];
            float tz = J[i][2] - J[p][2];
#pragma unroll
            for (int rr = 0; rr < 3; ++rr) {
                float w0 = W[p][rr * 4 + 0], w1 = W[p][rr * 4 + 1],
                      w2 = W[p][rr * 4 + 2], w3 = W[p][rr * 4 + 3];
#pragma unroll
                for (int cc = 0; cc < 3; ++cc)
                    W[i][rr * 4 + cc] = w0 * R[i][0 * 3 + cc] +
                                        w1 * R[i][1 * 3 + cc] +
                                        w2 * R[i][2 * 3 + cc];
                W[i][rr * 4 + 3] = w0 * tx + w1 * ty + w2 * tz + w3;
            }
        }
    }
    __syncthreads();

    if (t < NJ) {
        float* g = g_G + ((size_t)b * NJ + t) * 12;
#pragma unroll
        for (int rr = 0; rr < 3; ++rr) {
            float w0 = W[t][rr * 4 + 0], w1 = W[t][rr * 4 + 1],
                  w2 = W[t][rr * 4 + 2], w3 = W[t][rr * 4 + 3];
            g[rr * 4 + 0] = w0;
            g[rr * 4 + 1] = w1;
            g[rr * 4 + 2] = w2;
            g[rr * 4 + 3] = w3 - (w0 * J[t][0] + w1 * J[t][1] + w2 * J[t][2]);
        }
    }
    for (int idx = t; idx < NP; idx += 32) {
        int j = idx / 9 + 1;
        int rc = idx % 9;
        float v = R[j][rc];
        if (rc == 0 || rc == 4 || rc == 8) v -= 1.f;
        g_lrot[(size_t)b * NP + idx] = v;
    }
}

// ---------------------------------------------------------------------------
// Kernel C: fused shape+pose blend + LBS, f32x2, prefetch-pipelined.
// ---------------------------------------------------------------------------
__global__ __launch_bounds__(CBLK) void kC(const float* __restrict__ betas,
                                           const float* __restrict__ trans,
                                           float* __restrict__ out, int Btot) {
    __shared__ __align__(16) float lr_sh[NP][TB];
    __shared__ __align__(16) float2 G2[TBH][NJ][12];
    __shared__ __align__(16) float bet_sh[NB][TB];
    __shared__ __align__(16) float2 tr2[TBH][3];

    int b0 = blockIdx.y * TB;
    int bcnt = Btot - b0; if (bcnt > TB) bcnt = TB;

    for (int i = threadIdx.x; i < NP * TB; i += CBLK) {
        int p = i / TB, bb = i % TB;
        lr_sh[p][bb] = (bb < bcnt) ? g_lrot[(size_t)(b0 + bb) * NP + p] : 0.f;
    }
    for (int i = threadIdx.x; i < TBH * NJ * 12; i += CBLK) {
        int q = i / (NJ * 12), k = i % (NJ * 12);
        int be = 2 * q, bo = 2 * q + 1;
        float ge = (be < bcnt) ? g_G[(size_t)(b0 + be) * NJ * 12 + k] : 0.f;
        float go = (bo < bcnt) ? g_G[(size_t)(b0 + bo) * NJ * 12 + k] : 0.f;
        G2[q][k / 12][k % 12] = make_float2(ge, go);
    }
    for (int i = threadIdx.x; i < NB * TB; i += CBLK) {
        int s = i / TB, bb = i % TB;
        bet_sh[s][bb] = (bb < bcnt) ? betas[(b0 + bb) * NB + s] : 0.f;
    }
    for (int i = threadIdx.x; i < TBH * 3; i += CBLK) {
        int q = i / 3, c = i % 3;
        int be = 2 * q, bo = 2 * q + 1;
        float te = (be < bcnt) ? trans[(b0 + be) * 3 + c] : 0.f;
        float to = (bo < bcnt) ? trans[(b0 + bo) * 3 + c] : 0.f;
        tr2[q][c] = make_float2(te, to);
    }
    __syncthreads();

    int v = blockIdx.x * CBLK + threadIdx.x;
    if (v >= NVERT) return;

    // Early-issue long-latency loads used later (weights for LBS)
    float wv[NJ];
#pragma unroll
    for (int j = 0; j < NJ; ++j) wv[j] = __ldg(&g_wT[(size_t)j * NVERT + v]);

    // Accumulators initialized from v_template
    u64 A0[TBH], A1[TBH], A2[TBH];
    {
        u64 t0 = pack2(__ldg(&g_vtT[0 * NVERT + v]));
        u64 t1 = pack2(__ldg(&g_vtT[1 * NVERT + v]));
        u64 t2 = pack2(__ldg(&g_vtT[2 * NVERT + v]));
#pragma unroll
        for (int q = 0; q < TBH; ++q) { A0[q] = t0; A1[q] = t1; A2[q] = t2; }
    }

    // Shape blend
#pragma unroll
    for (int s = 0; s < NB; ++s) {
        u64 sa = pack2(__ldg(&g_sdT[(size_t)(0 * NB + s) * NVERT + v]));
        u64 sb = pack2(__ldg(&g_sdT[(size_t)(1 * NB + s) * NVERT + v]));
        u64 sc = pack2(__ldg(&g_sdT[(size_t)(2 * NB + s) * NVERT + v]));
        const ulonglong2* l = reinterpret_cast<const ulonglong2*>(bet_sh[s]);
#pragma unroll
        for (int h = 0; h < TBH / 2; ++h) {
            ulonglong2 lv = l[h];
            A0[2*h]   = fma2(sa, lv.x, A0[2*h]);
            A0[2*h+1] = fma2(sa, lv.y, A0[2*h+1]);
            A1[2*h]   = fma2(sb, lv.x, A1[2*h]);
            A1[2*h+1] = fma2(sb, lv.y, A1[2*h+1]);
            A2[2*h]   = fma2(sc, lv.x, A2[2*h]);
            A2[2*h+1] = fma2(sc, lv.y, A2[2*h+1]);
        }
    }

    // Pose blend: coalesced pd loads, software pipeline (prefetch distance 2)
    const float* pb0 = g_pdT + v;
    const float* pb1 = g_pdT + (size_t)NP * NVERT + v;
    const float* pb2 = g_pdT + (size_t)2 * NP * NVERT + v;

    float r0a = __ldg(pb0), r0b = __ldg(pb1), r0c = __ldg(pb2);
    float r1a = __ldg(pb0 + NVERT), r1b = __ldg(pb1 + NVERT), r1c = __ldg(pb2 + NVERT);

#pragma unroll 3
    for (int p = 0; p < NP; ++p) {
        float r2a = 0.f, r2b = 0.f, r2c = 0.f;
        if (p + 2 < NP) {
            size_t off = (size_t)(p + 2) * NVERT;
            r2a = __ldg(pb0 + off);
            r2b = __ldg(pb1 + off);
            r2c = __ldg(pb2 + off);
        }
        u64 pa = pack2(r0a), pbv = pack2(r0b), pc = pack2(r0c);
        const ulonglong2* l = reinterpret_cast<const ulonglong2*>(lr_sh[p]);
#pragma unroll
        for (int h = 0; h < TBH / 2; ++h) {
            ulonglong2 lv = l[h];
            A0[2*h]   = fma2(pa,  lv.x, A0[2*h]);
            A0[2*h+1] = fma2(pa,  lv.y, A0[2*h+1]);
            A1[2*h]   = fma2(pbv, lv.x, A1[2*h]);
            A1[2*h+1] = fma2(pbv, lv.y, A1[2*h+1]);
            A2[2*h]   = fma2(pc,  lv.x, A2[2*h]);
            A2[2*h+1] = fma2(pc,  lv.y, A2[2*h+1]);
        }
        r0a = r1a; r0b = r1b; r0c = r1c;
        r1a = r2a; r1b = r2b; r1c = r2c;
    }

    // LBS: per q, build blended transform T = sum_j w_j * G_j, then apply.
#pragma unroll
    for (int q = 0; q < TBH; ++q) {
        u64 T[12];
#pragma unroll
        for (int k = 0; k < 12; ++k) T[k] = 0ull;
        const ulonglong2* gq = reinterpret_cast<const ulonglong2*>(G2[q][0]);
#pragma unroll 4
        for (int j = 0; j < NJ; ++j) {
            u64 wj = pack2(wv[j]);
            const ulonglong2* g = gq + j * 6;
#pragma unroll
            for (int k = 0; k < 6; ++k) {
                ulonglong2 gg = g[k];
                T[2*k]   = fma2(wj, gg.x, T[2*k]);
                T[2*k+1] = fma2(wj, gg.y, T[2*k+1]);
            }
        }
        u64 ox = fma2(T[0], A0[q], fma2(T[1], A1[q], fma2(T[2], A2[q], T[3])));
        u64 oy = fma2(T[4], A0[q], fma2(T[5], A1[q], fma2(T[6], A2[q], T[7])));
        u64 oz = fma2(T[8], A0[q], fma2(T[9], A1[q], fma2(T[10], A2[q], T[11])));
        const u64* tq = reinterpret_cast<const u64*>(tr2[q]);
        ox = add2(ox, tq[0]);
        oy = add2(oy, tq[1]);
        oz = add2(oz, tq[2]);
        float xe, xo, ye, yo, ze, zo;
        unpack2(ox, xe, xo);
        unpack2(oy, ye, yo);
        unpack2(oz, ze, zo);
        int be = 2 * q, bo = 2 * q + 1;
        if (be < bcnt) {
            size_t o = ((size_t)(b0 + be) * NVERT + v) * 3;
            out[o + 0] = xe; out[o + 1] = ye; out[o + 2] = ze;
        }
        if (bo < bcnt) {
            size_t o = ((size_t)(b0 + bo) * NVERT + v) * 3;
            out[o + 0] = xo; out[o + 1] = yo; out[o + 2] = zo;
        }
    }
}

// ---------------------------------------------------------------------------
// Kernel Z: zero the joints region.
// ---------------------------------------------------------------------------
__global__ __launch_bounds__(256) void kZ(float* __restrict__ joints, int n) {
    int i = blockIdx.x * 256 + threadIdx.x;
    if (i < n) joints[i] = 0.f;
}

// ---------------------------------------------------------------------------
// Kernel D: joints = J_regressor @ result, grid (B, VSPL), atomic finish.
// ---------------------------------------------------------------------------
__global__ __launch_bounds__(256) void kD(const float* __restrict__ Jr,
                                          const float* __restrict__ result,
                                          float* __restrict__ joints) {
    int b = blockIdx.x;
    int sp = blockIdx.y;
    int v0 = sp * VCH;
    int v1 = v0 + VCH; if (v1 > NVERT) v1 = NVERT;

    float acc[NJ][3];
#pragma unroll
    for (int j = 0; j < NJ; ++j) { acc[j][0] = 0.f; acc[j][1] = 0.f; acc[j][2] = 0.f; }

    const float* rb = result + (size_t)b * NVERT * 3;
    for (int v = v0 + threadIdx.x; v < v1; v += 256) {
        float rx = rb[v * 3 + 0], ry = rb[v * 3 + 1], rz = rb[v * 3 + 2];
#pragma unroll
        for (int j = 0; j < NJ; ++j) {
            float w = __ldg(&Jr[j * NVERT + v]);
            acc[j][0] = fmaf(w, rx, acc[j][0]);
            acc[j][1] = fmaf(w, ry, acc[j][1]);
            acc[j][2] = fmaf(w, rz, acc[j][2]);
        }
    }
    __shared__ float sm[NJ * 3];
    if (threadIdx.x < NJ * 3) sm[threadIdx.x] = 0.f;
    __syncthreads();
#pragma unroll
    for (int j = 0; j < NJ; ++j) {
#pragma unroll
        for (int c = 0; c < 3; ++c) {
            float x = acc[j][c];
#pragma unroll
            for (int off = 16; off > 0; off >>= 1)
                x += __shfl_xor_sync(0xffffffffu, x, off);
            if ((threadIdx.x & 31) == 0) atomicAdd(&sm[j * 3 + c], x);
        }
    }
    __syncthreads();
    if (threadIdx.x < NJ * 3)
        atomicAdd(&joints[(size_t)b * NJ * 3 + threadIdx.x], sm[threadIdx.x]);
}

// ---------------------------------------------------------------------------
extern "C" void kernel_launch(void* const* d_in, const int* in_sizes, int n_in,
                              void* d_out, int out_size) {
    const float* betas  = (const float*)d_in[0];
    const float* thetas = (const float*)d_in[1];
    const float* trans  = (const float*)d_in[2];
    const float* scale  = (const float*)d_in[3];
    const float* vt     = (const float*)d_in[4];
    const float* sd     = (const float*)d_in[5];
    const float* pd     = (const float*)d_in[6];
    const float* Jr     = (const float*)d_in[7];
    const float* wgt    = (const float*)d_in[8];

    int Btot = in_sizes[0] / NB;
    float* out = (float*)d_out;
    float* joints = out + (size_t)Btot * NVERT * 3;

    {
        float* wT; cudaGetSymbolAddress((void**)&wT, g_wT);
        float* sdT; cudaGetSymbolAddress((void**)&sdT, g_sdT);
        float* vtT; cudaGetSymbolAddress((void**)&vtT, g_vtT);
        dim3 tb(32, 8);
        dim3 gpd((NP + 31) / 32, (NVERT + 31) / 32, 3);
        kTpd<<<gpd, tb>>>(pd);
        dim3 g2((NVERT + 31) / 32, 1);
        kT2<<<g2, tb>>>(wgt, wT, NJ);
        kT2<<<g2, tb>>>(sd, sdT, 3 * NB);
        kT2<<<g2, tb>>>(vt, vtT, 3);
    }

    kA<<<NJ, 256>>>(Jr);
    kB<<<Btot, 32>>>(betas, thetas, scale);
    int nj = Btot * NJ * 3;
    kZ<<<(nj + 255) / 256, 256>>>(joints, nj);
    dim3 gc((NVERT + CBLK - 1) / CBLK, (Btot + TB - 1) / TB);
    kC<<<gc, CBLK>>>(betas, trans, out, Btot);
    dim3 gd(Btot, VSPL);
    kD<<<gd, 256>>>(Jr, out, joints);
}